// round 15
// baseline (speedup 1.0000x reference)
#include <cuda_runtime.h>
#include <math.h>

// ---------------- constants ----------------
#define CELLS   1470         // 30ch * 7 * 7 pooling cells
#define HB      2048u        // half batch (used by k_dec2 pairing only)

// output layout: x_rec | mean | log_var | eta
#define MEAN_OFF 3211264
#define LV_OFF   8454144
#define ETA_OFF  13697024

// scratch (static device arrays; no allocations)
__device__ float         g_pooled[4096 * CELLS];
__device__ unsigned char g_zeta2 [4096 * CELLS];
__device__ float         g_s     [4096 * 1280];
__device__ float         g_s2    [4096 * CELLS];

// ---------------- threefry2x32 (KAT-verified) ----------------
__host__ __device__ __forceinline__ unsigned rotl32(unsigned x, int r) {
    return (x << r) | (x >> (32 - r));
}
__host__ __device__ inline void threefry(unsigned k0, unsigned k1,
                                         unsigned x0, unsigned x1,
                                         unsigned &o0, unsigned &o1) {
    unsigned k2 = k0 ^ k1 ^ 0x1BD11BDAu;
    unsigned v0 = x0 + k0, v1 = x1 + k1;
#define TFR4(a,b,c,d) \
    v0 += v1; v1 = rotl32(v1,a); v1 ^= v0; \
    v0 += v1; v1 = rotl32(v1,b); v1 ^= v0; \
    v0 += v1; v1 = rotl32(v1,c); v1 ^= v0; \
    v0 += v1; v1 = rotl32(v1,d); v1 ^= v0;
    TFR4(13,15,26,6);  v0 += k1; v1 += k2 + 1u;
    TFR4(17,29,16,24); v0 += k2; v1 += k0 + 2u;
    TFR4(13,15,26,6);  v0 += k0; v1 += k1 + 3u;
    TFR4(17,29,16,24); v0 += k1; v1 += k2 + 4u;
    TFR4(13,15,26,6);  v0 += k2; v1 += k0 + 5u;
#undef TFR4
    o0 = v0; o1 = v1;
}

// partitionable random_bits, 32-bit: one call per element, counter (0, i), fold = o0 ^ o1
__device__ __forceinline__ unsigned rbits32(unsigned k0, unsigned k1, unsigned i) {
    unsigned a, b;
    threefry(k0, k1, 0u, i, a, b);
    return a ^ b;
}

__device__ __forceinline__ float u01f(unsigned bits) {
    return __uint_as_float((bits >> 9) | 0x3f800000u) - 1.0f;
}
__device__ __forceinline__ float gumbelf(unsigned bits) {
    float u = fmaxf(u01f(bits), 1.17549435e-38f);
    return -logf(-logf(u));
}
__device__ __forceinline__ float normalf(unsigned bits) {
    float u = fmaxf(-0.99999994f, fmaf(u01f(bits), 2.0f, -0.99999994f));
    return 1.41421356237f * erfinvf(u);
}

// ---------------- K1: conv1 + pool MLPs + softmax + categorical x2 ----------------
// one block per image; each thread handles whole (c,n,m) cells
__global__ void __launch_bounds__(256)
k_enc1(const float* __restrict__ x, const float* __restrict__ conv_w,
       const float* __restrict__ pw1, const float* __restrict__ pw2,
       float* __restrict__ out,
       unsigned kp0, unsigned kp1, unsigned ku0, unsigned ku1)
{
    __shared__ float sx[784];
    __shared__ float sw[1920];
    __shared__ float sp1[81], sp2[81];
    int b = blockIdx.x, tid = threadIdx.x;
    for (int i = tid; i < 784; i += 256)  sx[i] = x[b*784+i];
    for (int i = tid; i < 1920; i += 256) sw[i] = conv_w[i];
    if (tid < 81) { sp1[tid] = pw1[tid]; sp2[tid] = pw2[tid]; }
    __syncthreads();

    float* eta_out = out + ETA_OFF;

    for (int cc = tid; cc < CELLS; cc += 256) {
        int c = cc / 49;
        int r = cc - c * 49;
        int n = r / 7, m = r - n * 7;

        // conv1 for the 3x3 tile (9 outputs)
        float t0[9];
#pragma unroll
        for (int q = 0; q < 9; q++) t0[q] = 0.f;
        const float* wc = sw + c * 64;
        int xb = (3 * n) * 28 + 3 * m;
        for (int rr = 0; rr < 10; ++rr) {
            float xa[10];
#pragma unroll
            for (int q = 0; q < 10; q++) xa[q] = sx[xb + rr * 28 + q];
#pragma unroll
            for (int dy = 0; dy < 3; ++dy) {
                int u = rr - dy;
                if (u >= 0 && u < 8) {
                    const float* wr = wc + u * 8;
#pragma unroll
                    for (int v = 0; v < 8; ++v) {
                        float w = wr[v];
#pragma unroll
                        for (int dx = 0; dx < 3; ++dx)
                            t0[dy*3+dx] = fmaf(xa[v+dx], w, t0[dy*3+dx]);
                    }
                }
            }
        }

        // pooling MLPs: h1 = tanh(W1 t), z = W2 h1, eta = softmax(z)
        float h1a[9];
#pragma unroll
        for (int o = 0; o < 9; o++) {
            float sa = 0.f;
#pragma unroll
            for (int t = 0; t < 9; t++) sa = fmaf(t0[t], sp1[o*9+t], sa);
            h1a[o] = tanhf(sa);
        }
        float za[9];
#pragma unroll
        for (int o = 0; o < 9; o++) {
            float sa = 0.f;
#pragma unroll
            for (int t = 0; t < 9; t++) sa = fmaf(h1a[t], sp2[o*9+t], sa);
            za[o] = sa;
        }
        float ma = za[0];
#pragma unroll
        for (int o = 1; o < 9; o++) ma = fmaxf(ma, za[o]);
        float ea[9], suma = 0.f;
#pragma unroll
        for (int o = 0; o < 9; o++) { ea[o] = expf(za[o] - ma); suma += ea[o]; }
        float le0[9];
        int ebase = (b * CELLS + cc) * 9;
#pragma unroll
        for (int o = 0; o < 9; o++) {
            float eta0 = ea[o] / suma;
            eta_out[ebase + o] = eta0;
            le0[o] = logf(eta0);
        }

        // categorical: zeta_pool (pick tile value) + zeta_unpool (store index)
        float bp = 0.f, bu = 0.f, pool0 = 0.f;
        int ziu = 0;
#pragma unroll
        for (int t = 0; t < 9; t++) {
            float v = le0[t] + gumbelf(rbits32(kp0, kp1, (unsigned)(ebase + t)));
            float w = le0[t] + gumbelf(rbits32(ku0, ku1, (unsigned)(ebase + t)));
            if (t == 0) { bp = v; pool0 = t0[0]; bu = w; ziu = 0; }
            else {
                if (v > bp) { bp = v; pool0 = t0[t]; }
                if (w > bu) { bu = w; ziu = t; }
            }
        }
        g_pooled[b * CELLS + cc] = pool0;
        g_zeta2 [b * CELLS + cc] = (unsigned char)ziu;
    }
}

// ---------------- K2: conv2 + code MLPs + reparameterized sample ----------------
// one block per image; 640 threads = (k in 0..79, oh in 0..7), two output halves
__global__ void __launch_bounds__(640)
k_enc2(const float* __restrict__ enc2_w,
       const float* __restrict__ h_w,  const float* __restrict__ h_b,
       const float* __restrict__ mean_w, const float* __restrict__ mean_b,
       const float* __restrict__ lv_w,   const float* __restrict__ lv_b,
       float* __restrict__ out, unsigned kc0, unsigned kc1)
{
    __shared__ float sp[1470];
    __shared__ float sc2[1280];
    __shared__ float shh[1280];
    int b = blockIdx.x, tid = threadIdx.x;
    for (int i = tid; i < 1470; i += 640) sp[i] = g_pooled[b*1470+i];
    __syncthreads();
    int k = tid >> 3, oh = tid & 7;

    // conv2 -> flat[16]
#pragma unroll
    for (int hlf = 0; hlf < 2; ++hlf) {
        int o = oh + hlf * 8;
        int i = o >> 2, j = o & 3;
        float a0 = 0.f;
        for (int ch = 0; ch < 30; ++ch) {
            const float* wp = enc2_w + (k * 30 + ch) * 16;
            const float* p0 = &sp[ch * 49 + i * 7 + j];
#pragma unroll
            for (int u = 0; u < 4; u++)
#pragma unroll
                for (int v = 0; v < 4; v++)
                    a0 = fmaf(p0[u*7+v], wp[u*4+v], a0);
        }
        sc2[k*16+o] = a0;
    }
    __syncthreads();

    // h = tanh(W_h flat + b)
#pragma unroll
    for (int hlf = 0; hlf < 2; ++hlf) {
        int o = oh + hlf * 8;
        const float* wp = h_w + (k*16+o)*16;
        float a0 = h_b[k*16+o];
#pragma unroll
        for (int i2 = 0; i2 < 16; i2++) a0 = fmaf(sc2[k*16+i2], wp[i2], a0);
        shh[k*16+o] = tanhf(a0);
    }
    __syncthreads();

    // mean, log_var, sample
#pragma unroll
    for (int hlf = 0; hlf < 2; ++hlf) {
        int o = oh + hlf * 8;
        const float* wm = mean_w + (k*16+o)*16;
        const float* wl = lv_w   + (k*16+o)*16;
        float m0 = mean_b[k*16+o];
        float l0 = lv_b[k*16+o];
#pragma unroll
        for (int i2 = 0; i2 < 16; i2++) {
            float hv = shh[k*16+i2];
            m0 = fmaf(hv, wm[i2], m0);
            l0 = fmaf(hv, wl[i2], l0);
        }
        int idx = b * 1280 + k * 16 + o;
        out[MEAN_OFF + idx] = m0;
        out[LV_OFF   + idx] = l0;
        g_s[idx] = m0 + expf(0.5f * l0) * normalf(rbits32(kc0, kc1, (unsigned)idx));
    }
}

// ---------------- K3: ConvTranspose dec2: s[80,4,4] -> s2[30,7,7] ----------------
// one block per image pair; threads (img, c, y), each computes a 7-wide row
__global__ void __launch_bounds__(448)
k_dec2(const float* __restrict__ dw)
{
    __shared__ float ss[2][1280];
    int b0 = blockIdx.x, b1 = b0 + (int)HB, tid = threadIdx.x;
    for (int i = tid; i < 1280; i += 448) {
        ss[0][i] = g_s[b0*1280+i];
        ss[1][i] = g_s[b1*1280+i];
    }
    __syncthreads();
    if (tid >= 420) return;
    int img = tid / 210;
    int r = tid - img * 210;
    int c = r / 7, yy = r - c * 7;
    const float* sb = ss[img];
    float y7[7];
#pragma unroll
    for (int q = 0; q < 7; q++) y7[q] = 0.f;
    for (int k = 0; k < 80; k++) {
        const float* sk = sb + k * 16;
        const float* wk = dw + (k * 30 + c) * 16;
#pragma unroll
        for (int u = 0; u < 4; u++) {
            int i = yy - u;
            if ((unsigned)i < 4u) {
                float s0 = sk[i*4+0], s1 = sk[i*4+1], s2 = sk[i*4+2], s3 = sk[i*4+3];
#pragma unroll
                for (int v = 0; v < 4; v++) {
                    float wv = __ldg(wk + u*4 + v);
                    y7[v+0] = fmaf(s0, wv, y7[v+0]);
                    y7[v+1] = fmaf(s1, wv, y7[v+1]);
                    y7[v+2] = fmaf(s2, wv, y7[v+2]);
                    y7[v+3] = fmaf(s3, wv, y7[v+3]);
                }
            }
        }
    }
    int b = img ? b1 : b0;
    float* o = g_s2 + b * 1470 + c * 49 + yy * 7;
#pragma unroll
    for (int q = 0; q < 7; q++) o[q] = y7[q];
}

// ---------------- K4: sparse unpool + ConvTranspose dec1 (gather) ----------------
// one block per image; 784 threads = one output pixel each
__global__ void __launch_bounds__(784)
k_dec1(const float* __restrict__ dw, float* __restrict__ out)
{
    __shared__ float  sval[CELLS];
    __shared__ uchar2 sryx[CELLS];
    __shared__ float  sw[1920];
    int b = blockIdx.x, tid = threadIdx.x;
    for (int i = tid; i < CELLS; i += 784) {
        int z = g_zeta2[b * CELLS + i];
        int rr = i % 49;
        int n = rr / 7, m = rr - n * 7;
        uchar2 p; p.x = (unsigned char)(3*n + z/3); p.y = (unsigned char)(3*m + z%3);
        sryx[i] = p;
        sval[i] = g_s2[b * CELLS + i];
    }
    for (int i = tid; i < 1920; i += 784) sw[i] = dw[i];
    __syncthreads();

    int y = tid / 28, x = tid - y * 28;
    int nlo = max(0, (y - 7) / 3), nhi = min(6, y / 3);
    int mlo = max(0, (x - 7) / 3), mhi = min(6, x / 3);
    float acc = 0.f;
    for (int c = 0; c < 30; ++c) {
        const float* wc = sw + c * 64;
        int cb = c * 49;
        for (int n = nlo; n <= nhi; ++n) {
            int nb = cb + n * 7;
#pragma unroll
            for (int m = 0; m < 7; ++m) {
                if (m < mlo || m > mhi) continue;
                int t = nb + m;
                uchar2 p = sryx[t];
                int py = y - (int)p.x, px = x - (int)p.y;
                if ((unsigned)(py | px) < 8u)
                    acc = fmaf(sval[t], wc[py * 8 + px], acc);
            }
        }
    }
    out[b * 784 + tid] = acc;
}

// ---------------- K5: diagonal noise ----------------
__global__ void __launch_bounds__(256)
k_noise(float* __restrict__ out, const float* __restrict__ alpha,
        unsigned kn0, unsigned kn1)
{
    int g = blockIdx.x * 256 + threadIdx.x;
    if (g >= 4096 * 28) return;
    int b = g / 28, i = g - b * 28;
    unsigned idx = (unsigned)(b * 784 + i * 29);
    float inv = 1.0f / alpha[0];
    out[idx] += inv * normalf(rbits32(kn0, kn1, idx));
}

// ---------------- launch ----------------
extern "C" void kernel_launch(void* const* d_in, const int* in_sizes, int n_in,
                              void* d_out, int out_size) {
    const float* x       = (const float*)d_in[0];
    const float* enc1_w  = (const float*)d_in[1];
    const float* pool_w1 = (const float*)d_in[2];
    const float* pool_w2 = (const float*)d_in[3];
    const float* enc2_w  = (const float*)d_in[4];
    const float* h_w     = (const float*)d_in[5];
    const float* h_b     = (const float*)d_in[6];
    const float* mean_w  = (const float*)d_in[7];
    const float* mean_b  = (const float*)d_in[8];
    const float* lv_w    = (const float*)d_in[9];
    const float* lv_b    = (const float*)d_in[10];
    const float* dec2_w  = (const float*)d_in[11];
    const float* dec1_w  = (const float*)d_in[12];
    const float* alpha   = (const float*)d_in[13];
    float* out = (float*)d_out;

    // split(key(42), 4) under jax_threefry_partitionable (default since JAX 0.4.36):
    // subkey i = threefry((0,42), (0, i)) -> (out0, out1)
    unsigned kp0, kp1, ku0, ku1, kc0, kc1, kn0, kn1;
    threefry(0u, 42u, 0u, 0u, kp0, kp1);   // k_pool
    threefry(0u, 42u, 0u, 1u, ku0, ku1);   // k_unpool
    threefry(0u, 42u, 0u, 2u, kc0, kc1);   // k_code
    threefry(0u, 42u, 0u, 3u, kn0, kn1);   // k_noise

    k_enc1<<<4096, 256>>>(x, enc1_w, pool_w1, pool_w2, out, kp0, kp1, ku0, ku1);
    k_enc2<<<4096, 640>>>(enc2_w, h_w, h_b, mean_w, mean_b, lv_w, lv_b, out, kc0, kc1);
    k_dec2<<<HB, 448>>>(dec2_w);
    k_dec1<<<4096, 784>>>(dec1_w, out);
    k_noise<<<(4096 * 28 + 255) / 256, 256>>>(out, alpha, kn0, kn1);
}

// round 16
// speedup vs baseline: 1.1683x; 1.1683x over previous
#include <cuda_runtime.h>
#include <math.h>

// ---------------- constants ----------------
#define CELLS   1470         // 30ch * 7 * 7 pooling cells
#define HB      2048u        // half batch (k_dec2 pairing)

// output layout: x_rec | mean | log_var | eta
#define MEAN_OFF 3211264
#define LV_OFF   8454144
#define ETA_OFF  13697024

// scratch (static device arrays; no allocations)
__device__ float         g_pooled[4096 * CELLS];
__device__ unsigned char g_zeta2 [4096 * CELLS];
__device__ float         g_s     [4096 * 1280];
__device__ float         g_s2    [4096 * CELLS];

// ---------------- threefry2x32 (KAT-verified) ----------------
__host__ __device__ __forceinline__ unsigned rotl32(unsigned x, int r) {
    return (x << r) | (x >> (32 - r));
}
__host__ __device__ inline void threefry(unsigned k0, unsigned k1,
                                         unsigned x0, unsigned x1,
                                         unsigned &o0, unsigned &o1) {
    unsigned k2 = k0 ^ k1 ^ 0x1BD11BDAu;
    unsigned v0 = x0 + k0, v1 = x1 + k1;
#define TFR4(a,b,c,d) \
    v0 += v1; v1 = rotl32(v1,a); v1 ^= v0; \
    v0 += v1; v1 = rotl32(v1,b); v1 ^= v0; \
    v0 += v1; v1 = rotl32(v1,c); v1 ^= v0; \
    v0 += v1; v1 = rotl32(v1,d); v1 ^= v0;
    TFR4(13,15,26,6);  v0 += k1; v1 += k2 + 1u;
    TFR4(17,29,16,24); v0 += k2; v1 += k0 + 2u;
    TFR4(13,15,26,6);  v0 += k0; v1 += k1 + 3u;
    TFR4(17,29,16,24); v0 += k1; v1 += k2 + 4u;
    TFR4(13,15,26,6);  v0 += k2; v1 += k0 + 5u;
#undef TFR4
    o0 = v0; o1 = v1;
}

// partitionable random_bits, 32-bit: counter (0, i), fold = o0 ^ o1
__device__ __forceinline__ unsigned rbits32(unsigned k0, unsigned k1, unsigned i) {
    unsigned a, b;
    threefry(k0, k1, 0u, i, a, b);
    return a ^ b;
}

__device__ __forceinline__ float u01f(unsigned bits) {
    return __uint_as_float((bits >> 9) | 0x3f800000u) - 1.0f;
}
__device__ __forceinline__ float gumbelf(unsigned bits) {
    float u = fmaxf(u01f(bits), 1.17549435e-38f);
    return -logf(-logf(u));
}
__device__ __forceinline__ float normalf(unsigned bits) {
    float u = fmaxf(-0.99999994f, fmaf(u01f(bits), 2.0f, -0.99999994f));
    return 1.41421356237f * erfinvf(u);
}

// ---------------- K1: conv1 + pool MLPs + softmax + categorical x2 ----------------
__global__ void __launch_bounds__(256)
k_enc1(const float* __restrict__ x, const float* __restrict__ conv_w,
       const float* __restrict__ pw1, const float* __restrict__ pw2,
       float* __restrict__ out,
       unsigned kp0, unsigned kp1, unsigned ku0, unsigned ku1)
{
    __shared__ float sx[784];
    __shared__ float sw[1920];
    __shared__ float sp1[81], sp2[81];
    int b = blockIdx.x, tid = threadIdx.x;
    for (int i = tid; i < 784; i += 256)  sx[i] = x[b*784+i];
    for (int i = tid; i < 1920; i += 256) sw[i] = conv_w[i];
    if (tid < 81) { sp1[tid] = pw1[tid]; sp2[tid] = pw2[tid]; }
    __syncthreads();

    float* eta_out = out + ETA_OFF;

    for (int cc = tid; cc < CELLS; cc += 256) {
        int c = cc / 49;
        int r = cc - c * 49;
        int n = r / 7, m = r - n * 7;

        // conv1 for the 3x3 tile (9 outputs)
        float t0[9];
#pragma unroll
        for (int q = 0; q < 9; q++) t0[q] = 0.f;
        const float* wc = sw + c * 64;
        int xb = (3 * n) * 28 + 3 * m;
        for (int rr = 0; rr < 10; ++rr) {
            float xa[10];
#pragma unroll
            for (int q = 0; q < 10; q++) xa[q] = sx[xb + rr * 28 + q];
#pragma unroll
            for (int dy = 0; dy < 3; ++dy) {
                int u = rr - dy;
                if (u >= 0 && u < 8) {
                    const float* wr = wc + u * 8;
#pragma unroll
                    for (int v = 0; v < 8; ++v) {
                        float w = wr[v];
#pragma unroll
                        for (int dx = 0; dx < 3; ++dx)
                            t0[dy*3+dx] = fmaf(xa[v+dx], w, t0[dy*3+dx]);
                    }
                }
            }
        }

        // pooling MLPs: h1 = tanh(W1 t), z = W2 h1, eta = softmax(z)
        float h1a[9];
#pragma unroll
        for (int o = 0; o < 9; o++) {
            float sa = 0.f;
#pragma unroll
            for (int t = 0; t < 9; t++) sa = fmaf(t0[t], sp1[o*9+t], sa);
            h1a[o] = tanhf(sa);
        }
        float za[9];
#pragma unroll
        for (int o = 0; o < 9; o++) {
            float sa = 0.f;
#pragma unroll
            for (int t = 0; t < 9; t++) sa = fmaf(h1a[t], sp2[o*9+t], sa);
            za[o] = sa;
        }
        float ma = za[0];
#pragma unroll
        for (int o = 1; o < 9; o++) ma = fmaxf(ma, za[o]);
        float ea[9], suma = 0.f;
#pragma unroll
        for (int o = 0; o < 9; o++) { ea[o] = expf(za[o] - ma); suma += ea[o]; }
        float le0[9];
        int ebase = (b * CELLS + cc) * 9;
#pragma unroll
        for (int o = 0; o < 9; o++) {
            float eta0 = ea[o] / suma;
            eta_out[ebase + o] = eta0;
            le0[o] = logf(eta0);
        }

        // categorical: zeta_pool (pick tile value) + zeta_unpool (store index)
        float bp = 0.f, bu = 0.f, pool0 = 0.f;
        int ziu = 0;
#pragma unroll
        for (int t = 0; t < 9; t++) {
            float v = le0[t] + gumbelf(rbits32(kp0, kp1, (unsigned)(ebase + t)));
            float w = le0[t] + gumbelf(rbits32(ku0, ku1, (unsigned)(ebase + t)));
            if (t == 0) { bp = v; pool0 = t0[0]; bu = w; ziu = 0; }
            else {
                if (v > bp) { bp = v; pool0 = t0[t]; }
                if (w > bu) { bu = w; ziu = t; }
            }
        }
        g_pooled[b * CELLS + cc] = pool0;
        g_zeta2 [b * CELLS + cc] = (unsigned char)ziu;
    }
}

// ---------------- K2: conv2 + code MLPs + reparameterized sample ----------------
__global__ void __launch_bounds__(640)
k_enc2(const float* __restrict__ enc2_w,
       const float* __restrict__ h_w,  const float* __restrict__ h_b,
       const float* __restrict__ mean_w, const float* __restrict__ mean_b,
       const float* __restrict__ lv_w,   const float* __restrict__ lv_b,
       float* __restrict__ out, unsigned kc0, unsigned kc1)
{
    __shared__ float sp[1470];
    __shared__ float sc2[1280];
    __shared__ float shh[1280];
    int b = blockIdx.x, tid = threadIdx.x;
    for (int i = tid; i < 1470; i += 640) sp[i] = g_pooled[b*1470+i];
    __syncthreads();
    int k = tid >> 3, oh = tid & 7;

#pragma unroll
    for (int hlf = 0; hlf < 2; ++hlf) {
        int o = oh + hlf * 8;
        int i = o >> 2, j = o & 3;
        float a0 = 0.f;
        for (int ch = 0; ch < 30; ++ch) {
            const float* wp = enc2_w + (k * 30 + ch) * 16;
            const float* p0 = &sp[ch * 49 + i * 7 + j];
#pragma unroll
            for (int u = 0; u < 4; u++)
#pragma unroll
                for (int v = 0; v < 4; v++)
                    a0 = fmaf(p0[u*7+v], wp[u*4+v], a0);
        }
        sc2[k*16+o] = a0;
    }
    __syncthreads();

#pragma unroll
    for (int hlf = 0; hlf < 2; ++hlf) {
        int o = oh + hlf * 8;
        const float* wp = h_w + (k*16+o)*16;
        float a0 = h_b[k*16+o];
#pragma unroll
        for (int i2 = 0; i2 < 16; i2++) a0 = fmaf(sc2[k*16+i2], wp[i2], a0);
        shh[k*16+o] = tanhf(a0);
    }
    __syncthreads();

#pragma unroll
    for (int hlf = 0; hlf < 2; ++hlf) {
        int o = oh + hlf * 8;
        const float* wm = mean_w + (k*16+o)*16;
        const float* wl = lv_w   + (k*16+o)*16;
        float m0 = mean_b[k*16+o];
        float l0 = lv_b[k*16+o];
#pragma unroll
        for (int i2 = 0; i2 < 16; i2++) {
            float hv = shh[k*16+i2];
            m0 = fmaf(hv, wm[i2], m0);
            l0 = fmaf(hv, wl[i2], l0);
        }
        int idx = b * 1280 + k * 16 + o;
        out[MEAN_OFF + idx] = m0;
        out[LV_OFF   + idx] = l0;
        g_s[idx] = m0 + expf(0.5f * l0) * normalf(rbits32(kc0, kc1, (unsigned)idx));
    }
}

// ---------------- K3: ConvTranspose dec2: s[80,4,4] -> s2[30,7,7] ----------------
__global__ void __launch_bounds__(448)
k_dec2(const float* __restrict__ dw)
{
    __shared__ float ss[2][1280];
    int b0 = blockIdx.x, b1 = b0 + (int)HB, tid = threadIdx.x;
    for (int i = tid; i < 1280; i += 448) {
        ss[0][i] = g_s[b0*1280+i];
        ss[1][i] = g_s[b1*1280+i];
    }
    __syncthreads();
    if (tid >= 420) return;
    int img = tid / 210;
    int r = tid - img * 210;
    int c = r / 7, yy = r - c * 7;
    const float* sb = ss[img];
    float y7[7];
#pragma unroll
    for (int q = 0; q < 7; q++) y7[q] = 0.f;
    for (int k = 0; k < 80; k++) {
        const float* sk = sb + k * 16;
        const float* wk = dw + (k * 30 + c) * 16;
#pragma unroll
        for (int u = 0; u < 4; u++) {
            int i = yy - u;
            if ((unsigned)i < 4u) {
                float s0 = sk[i*4+0], s1 = sk[i*4+1], s2 = sk[i*4+2], s3 = sk[i*4+3];
#pragma unroll
                for (int v = 0; v < 4; v++) {
                    float wv = __ldg(wk + u*4 + v);
                    y7[v+0] = fmaf(s0, wv, y7[v+0]);
                    y7[v+1] = fmaf(s1, wv, y7[v+1]);
                    y7[v+2] = fmaf(s2, wv, y7[v+2]);
                    y7[v+3] = fmaf(s3, wv, y7[v+3]);
                }
            }
        }
    }
    int b = img ? b1 : b0;
    float* o = g_s2 + b * 1470 + c * 49 + yy * 7;
#pragma unroll
    for (int q = 0; q < 7; q++) o[q] = y7[q];
}

// ---------------- K4: sparse unpool + ConvTranspose dec1 + diagonal noise ----------------
// 2 images per block; each thread computes a 2x2 output-pixel quad.
// Contributing FMAs execute in the same c -> n -> m order as the reference
// per-pixel gather, so accumulation is bitwise identical.
__global__ void __launch_bounds__(392)
k_dec1(const float* __restrict__ dw, const float* __restrict__ alpha,
       float* __restrict__ out, unsigned kn0, unsigned kn1)
{
    __shared__ float  sval[2][CELLS];
    __shared__ uchar2 sryx[2][CELLS];
    __shared__ float  sw[1920];
    int bp = blockIdx.x;            // image pair (2*bp, 2*bp+1)
    int tid = threadIdx.x;          // 0..391
    int b0 = bp * 2;
    for (int i = tid; i < 2 * CELLS; i += 392) {
        int im = i / CELLS, t = i - im * CELLS;
        int bb = b0 + im;
        int z = g_zeta2[bb * CELLS + t];
        int rr = t % 49;
        int n = rr / 7, m = rr - n * 7;
        uchar2 p;
        p.x = (unsigned char)(3 * n + z / 3);
        p.y = (unsigned char)(3 * m + z % 3);
        sryx[im][t] = p;
        sval[im][t] = g_s2[bb * CELLS + t];
    }
    for (int i = tid; i < 1920; i += 392) sw[i] = dw[i];
    __syncthreads();

    int img = tid / 196;
    int q = tid - img * 196;
    int qy = q / 14, qx = q - qy * 14;
    int y0 = qy * 2, x0 = qx * 2;

    // candidate tile ranges covering both rows {y0, y0+1} / cols {x0, x0+1}
    int nlo = max(0, (y0 - 7) / 3), nhi = min(6, (y0 + 1) / 3);
    int mlo = max(0, (x0 - 7) / 3), mhi = min(6, (x0 + 1) / 3);

    float a00 = 0.f, a01 = 0.f, a10 = 0.f, a11 = 0.f;
    for (int c = 0; c < 30; ++c) {
        const float* wc = sw + c * 64;
        int cb = c * 49;
        for (int n = nlo; n <= nhi; ++n) {
            int nb = cb + n * 7;
            for (int m = mlo; m <= mhi; ++m) {
                int t = nb + m;
                uchar2 p = sryx[img][t];
                float v = sval[img][t];
                int py = y0 - (int)p.x;
                int px = x0 - (int)p.y;
                if ((unsigned)py < 8u) {
                    const float* wr = wc + py * 8;
                    if ((unsigned)px < 8u)       a00 = fmaf(v, wr[px],     a00);
                    if ((unsigned)(px + 1) < 8u) a01 = fmaf(v, wr[px + 1], a01);
                }
                int py1 = py + 1;
                if ((unsigned)py1 < 8u) {
                    const float* wr = wc + py1 * 8;
                    if ((unsigned)px < 8u)       a10 = fmaf(v, wr[px],     a10);
                    if ((unsigned)(px + 1) < 8u) a11 = fmaf(v, wr[px + 1], a11);
                }
            }
        }
    }

    int b = b0 + img;
    // fused diagonal noise: diag pixels exist only in qy==qx quads (parity)
    if (qy == qx) {
        float inv = 1.0f / alpha[0];
        unsigned i0 = (unsigned)(b * 784 + y0 * 29);
        unsigned i1 = (unsigned)(b * 784 + (y0 + 1) * 29);
        a00 = a00 + inv * normalf(rbits32(kn0, kn1, i0));
        a11 = a11 + inv * normalf(rbits32(kn0, kn1, i1));
    }
    float* o = out + b * 784 + y0 * 28 + x0;
    o[0]  = a00; o[1]  = a01;
    o[28] = a10; o[29] = a11;
}

// ---------------- launch ----------------
extern "C" void kernel_launch(void* const* d_in, const int* in_sizes, int n_in,
                              void* d_out, int out_size) {
    const float* x       = (const float*)d_in[0];
    const float* enc1_w  = (const float*)d_in[1];
    const float* pool_w1 = (const float*)d_in[2];
    const float* pool_w2 = (const float*)d_in[3];
    const float* enc2_w  = (const float*)d_in[4];
    const float* h_w     = (const float*)d_in[5];
    const float* h_b     = (const float*)d_in[6];
    const float* mean_w  = (const float*)d_in[7];
    const float* mean_b  = (const float*)d_in[8];
    const float* lv_w    = (const float*)d_in[9];
    const float* lv_b    = (const float*)d_in[10];
    const float* dec2_w  = (const float*)d_in[11];
    const float* dec1_w  = (const float*)d_in[12];
    const float* alpha   = (const float*)d_in[13];
    float* out = (float*)d_out;

    // split(key(42), 4) under jax_threefry_partitionable:
    // subkey i = threefry((0,42), (0, i)) -> (out0, out1)
    unsigned kp0, kp1, ku0, ku1, kc0, kc1, kn0, kn1;
    threefry(0u, 42u, 0u, 0u, kp0, kp1);   // k_pool
    threefry(0u, 42u, 0u, 1u, ku0, ku1);   // k_unpool
    threefry(0u, 42u, 0u, 2u, kc0, kc1);   // k_code
    threefry(0u, 42u, 0u, 3u, kn0, kn1);   // k_noise

    k_enc1<<<4096, 256>>>(x, enc1_w, pool_w1, pool_w2, out, kp0, kp1, ku0, ku1);
    k_enc2<<<4096, 640>>>(enc2_w, h_w, h_b, mean_w, mean_b, lv_w, lv_b, out, kc0, kc1);
    k_dec2<<<HB, 448>>>(dec2_w);
    k_dec1<<<HB, 392>>>(dec1_w, alpha, out, kn0, kn1);
}